// round 6
// baseline (speedup 1.0000x reference)
#include <cuda_runtime.h>
#include <cuda_bf16.h>
#include <cstddef>
#include <cstdint>

// Problem constants
#define EMBED  1024
#define NHEADS 16
#define HDIM   64
#define BATCH  4
#define SEQ    2048
#define MROWS  (BATCH * SEQ)          // 8192
#define K3     (3 * EMBED)            // 3072 (bf16x3-split expanded K)

// ---------------------------------------------------------------------------
// Scratch (device globals: allocation-free per harness rules)
// ---------------------------------------------------------------------------
__device__ float          g_qkv[(size_t)MROWS * 3 * EMBED];     // GEMM1 out (f32)
__device__ float          g_ctx[(size_t)MROWS * EMBED];         // attn out (f32)
__device__ __nv_bfloat16  g_a3[(size_t)MROWS * K3];             // split acts (x, then ctx)
__device__ __nv_bfloat16  g_w1[(size_t)K3 * (3 * EMBED)];       // split Wqkv  [3072][3072]
__device__ __nv_bfloat16  g_w2[(size_t)K3 * EMBED];             // split Wout  [3072][1024]
// attention operands, head-contiguous [b*H+h][t][...]
__device__ __nv_bfloat16  g_q3[(size_t)BATCH * NHEADS * SEQ * 192];  // [Qhi|Qhi|Qlo] (pre-scaled)
__device__ __nv_bfloat16  g_k3[(size_t)BATCH * NHEADS * SEQ * 192];  // [Khi|Klo|Khi]
__device__ __nv_bfloat16  g_vh[(size_t)BATCH * NHEADS * SEQ * HDIM];
__device__ __nv_bfloat16  g_vl[(size_t)BATCH * NHEADS * SEQ * HDIM];

__device__ __forceinline__ uint32_t smem_u32(const void* p) {
    return (uint32_t)__cvta_generic_to_shared(p);
}

// ---------------------------------------------------------------------------
// bf16x3 split conversions (Markidis): v = hi + lo, error ~2^-18 rel
// ---------------------------------------------------------------------------
__global__ void split3_act(const float* __restrict__ src,
                           __nv_bfloat16* __restrict__ dst, int M, int K)
{
    int idx = blockIdx.x * blockDim.x + threadIdx.x;
    if (idx >= M * K) return;
    int m = idx / K, k = idx - m * K;
    float v = src[idx];
    __nv_bfloat16 hi = __float2bfloat16(v);
    __nv_bfloat16 lo = __float2bfloat16(v - __bfloat162float(hi));
    size_t base = (size_t)m * (3 * K);
    dst[base + k]         = hi;
    dst[base + K + k]     = hi;
    dst[base + 2 * K + k] = lo;
}

__global__ void split3_wt(const float* __restrict__ src,
                          __nv_bfloat16* __restrict__ dst, int K, int N)
{
    int idx = blockIdx.x * blockDim.x + threadIdx.x;
    if (idx >= K * N) return;
    int k = idx / N, n = idx - k * N;
    float v = src[idx];
    __nv_bfloat16 hi = __float2bfloat16(v);
    __nv_bfloat16 lo = __float2bfloat16(v - __bfloat162float(hi));
    dst[(size_t)k * N + n]           = hi;
    dst[(size_t)(K + k) * N + n]     = lo;
    dst[(size_t)(2 * K + k) * N + n] = hi;
}

// Split qkv (f32, [m][3072]) into per-head attention operands.
// Q is pre-scaled by (1/sqrt(d))*log2(e). One thread per (m, h, d).
__global__ void split_attn(const float* __restrict__ qkv,
                           __nv_bfloat16* __restrict__ q3,
                           __nv_bfloat16* __restrict__ k3,
                           __nv_bfloat16* __restrict__ vh,
                           __nv_bfloat16* __restrict__ vl)
{
    int idx = blockIdx.x * blockDim.x + threadIdx.x;
    if (idx >= MROWS * EMBED) return;
    int m = idx >> 10;                 // /1024
    int r = idx & 1023;
    int h = r >> 6;                    // /64
    int d = r & 63;
    int b = m / SEQ, t = m - b * SEQ;
    const float SC = 0.125f * 1.44269504088896340736f;

    float qv = qkv[(size_t)m * K3 + h * HDIM + d] * SC;
    float kv = qkv[(size_t)m * K3 + EMBED + h * HDIM + d];
    float vv = qkv[(size_t)m * K3 + 2 * EMBED + h * HDIM + d];

    size_t row = (size_t)(b * NHEADS + h) * SEQ + t;

    __nv_bfloat16 qh = __float2bfloat16(qv);
    __nv_bfloat16 ql = __float2bfloat16(qv - __bfloat162float(qh));
    q3[row * 192 + d]       = qh;
    q3[row * 192 + 64 + d]  = qh;
    q3[row * 192 + 128 + d] = ql;

    __nv_bfloat16 kh = __float2bfloat16(kv);
    __nv_bfloat16 kl = __float2bfloat16(kv - __bfloat162float(kh));
    k3[row * 192 + d]       = kh;
    k3[row * 192 + 64 + d]  = kl;
    k3[row * 192 + 128 + d] = kh;

    __nv_bfloat16 vhv = __float2bfloat16(vv);
    __nv_bfloat16 vlv = __float2bfloat16(vv - __bfloat162float(vhv));
    vh[row * HDIM + d] = vhv;
    vl[row * HDIM + d] = vlv;
}

// ---------------------------------------------------------------------------
// bf16 tensor-core GEMM + bias (UNCHANGED from R4, audited)
// ---------------------------------------------------------------------------
#define GBM 128
#define GBN 128
#define GBK 32

__global__ __launch_bounds__(256, 2)
void gemm_bf16_mma(const __nv_bfloat16* __restrict__ A,   // [M][K3]
                   const __nv_bfloat16* __restrict__ B,   // [K3][N]
                   const float* __restrict__ bias,
                   float* __restrict__ C,
                   int M, int N)
{
    __shared__ __nv_bfloat16 As[2][GBM][GBK + 8];   // row stride 80B
    __shared__ __nv_bfloat16 Bs[2][GBK][GBN + 8];   // row stride 272B

    const int tid  = threadIdx.x;
    const int lane = tid & 31;
    const int warp = tid >> 5;
    const int wm   = warp >> 2;
    const int wn   = warp & 3;
    const int bm   = blockIdx.y * GBM;
    const int bn   = blockIdx.x * GBN;

    const int ar0 = tid >> 2,          ac0 = (tid & 3) * 8;
    const int ar1 = (tid + 256) >> 2,  ac1 = (tid & 3) * 8;
    const int br0 = tid >> 4,          bc0 = (tid & 15) * 8;
    const int br1 = 16 + (tid >> 4),   bc1 = (tid & 15) * 8;

    float acc[4][4][4];
#pragma unroll
    for (int mi = 0; mi < 4; mi++)
#pragma unroll
        for (int ni = 0; ni < 4; ni++)
#pragma unroll
            for (int r = 0; r < 4; r++) acc[mi][ni][r] = 0.0f;

    {
        uint4 va0 = *(const uint4*)&A[(size_t)(bm + ar0) * K3 + 0 + ac0];
        uint4 va1 = *(const uint4*)&A[(size_t)(bm + ar1) * K3 + 0 + ac1];
        uint4 vb0 = *(const uint4*)&B[(size_t)(0 + br0) * N + bn + bc0];
        uint4 vb1 = *(const uint4*)&B[(size_t)(0 + br1) * N + bn + bc1];
        *(uint4*)&As[0][ar0][ac0] = va0;
        *(uint4*)&As[0][ar1][ac1] = va1;
        *(uint4*)&Bs[0][br0][bc0] = vb0;
        *(uint4*)&Bs[0][br1][bc1] = vb1;
    }
    __syncthreads();

    int buf = 0;
    for (int k0 = 0; k0 < K3; k0 += GBK) {
        const bool has_next = (k0 + GBK) < K3;
        uint4 va0, va1, vb0, vb1;
        if (has_next) {
            const int kn = k0 + GBK;
            va0 = *(const uint4*)&A[(size_t)(bm + ar0) * K3 + kn + ac0];
            va1 = *(const uint4*)&A[(size_t)(bm + ar1) * K3 + kn + ac1];
            vb0 = *(const uint4*)&B[(size_t)(kn + br0) * N + bn + bc0];
            vb1 = *(const uint4*)&B[(size_t)(kn + br1) * N + bn + bc1];
        }

#pragma unroll
        for (int ks = 0; ks < 2; ks++) {
            const int k16 = ks * 16;
            uint32_t a[4][4];
#pragma unroll
            for (int mi = 0; mi < 4; mi++) {
                uint32_t addr = smem_u32(
                    &As[buf][wm * 64 + mi * 16 + (lane & 15)]
                            [k16 + ((lane >> 4) << 3)]);
                asm volatile(
                    "ldmatrix.sync.aligned.m8n8.x4.shared.b16 {%0,%1,%2,%3}, [%4];"
                    : "=r"(a[mi][0]), "=r"(a[mi][1]), "=r"(a[mi][2]), "=r"(a[mi][3])
                    : "r"(addr));
            }
            uint32_t b[4][2];
#pragma unroll
            for (int n2 = 0; n2 < 2; n2++) {
                uint32_t addr = smem_u32(
                    &Bs[buf][k16 + (lane & 15)]
                            [wn * 32 + n2 * 16 + ((lane >> 4) << 3)]);
                uint32_t t0, t1, t2, t3;
                asm volatile(
                    "ldmatrix.sync.aligned.m8n8.x4.trans.shared.b16 {%0,%1,%2,%3}, [%4];"
                    : "=r"(t0), "=r"(t1), "=r"(t2), "=r"(t3)
                    : "r"(addr));
                b[n2 * 2][0]     = t0;  b[n2 * 2][1]     = t1;
                b[n2 * 2 + 1][0] = t2;  b[n2 * 2 + 1][1] = t3;
            }
#pragma unroll
            for (int mi = 0; mi < 4; mi++)
#pragma unroll
                for (int ni = 0; ni < 4; ni++)
                    asm volatile(
                        "mma.sync.aligned.m16n8k16.row.col.f32.bf16.bf16.f32 "
                        "{%0,%1,%2,%3}, {%4,%5,%6,%7}, {%8,%9}, {%0,%1,%2,%3};"
                        : "+f"(acc[mi][ni][0]), "+f"(acc[mi][ni][1]),
                          "+f"(acc[mi][ni][2]), "+f"(acc[mi][ni][3])
                        : "r"(a[mi][0]), "r"(a[mi][1]), "r"(a[mi][2]), "r"(a[mi][3]),
                          "r"(b[ni][0]), "r"(b[ni][1]));
        }

        if (has_next) {
            const int nb = buf ^ 1;
            *(uint4*)&As[nb][ar0][ac0] = va0;
            *(uint4*)&As[nb][ar1][ac1] = va1;
            *(uint4*)&Bs[nb][br0][bc0] = vb0;
            *(uint4*)&Bs[nb][br1][bc1] = vb1;
            __syncthreads();
            buf = nb;
        }
    }

    const int g  = lane >> 2;
    const int tg = lane & 3;
#pragma unroll
    for (int mi = 0; mi < 4; mi++) {
        const int row0 = bm + wm * 64 + mi * 16 + g;
#pragma unroll
        for (int ni = 0; ni < 4; ni++) {
            const int col = bn + wn * 32 + ni * 8 + tg * 2;
            const float bx = bias[col], by = bias[col + 1];
            float2 v0 = make_float2(acc[mi][ni][0] + bx, acc[mi][ni][1] + by);
            float2 v1 = make_float2(acc[mi][ni][2] + bx, acc[mi][ni][3] + by);
            *(float2*)&C[(size_t)row0 * N + col]       = v0;
            *(float2*)&C[(size_t)(row0 + 8) * N + col] = v1;
        }
    }
}

// ---------------------------------------------------------------------------
// FA2-style attention on tensor cores, bf16x3 splits, base-2 softmax.
// CTA: 128 q rows, 4 warps x 32 rows. Key tile KT=64.
// S = Q3[128,192] @ K3^T  (K as mma-B via NON-trans ldmatrix: pairing {t0,t2},{t1,t3})
// O += Phi@Vhi + Phi@Vlo + Plo@Vhi (V as mma-B via trans ldmatrix: {t0,t1},{t2,t3})
// smem (dynamic, 95488B): Qs[128][200], Ks[64][200], Vh[64][72], Vl[64][72], Ms[64]
// ---------------------------------------------------------------------------
#define ATT_SMEM ((128*200 + 64*200 + 2*64*72) * 2 + 64 * 4)

__global__ __launch_bounds__(128)
void attn_mma(const __nv_bfloat16* __restrict__ q3,
              const __nv_bfloat16* __restrict__ k3,
              const __nv_bfloat16* __restrict__ vhi,
              const __nv_bfloat16* __restrict__ vlo,
              const int* __restrict__ mask,
              float* __restrict__ ctx)
{
    extern __shared__ __nv_bfloat16 sm[];
    __nv_bfloat16* Qs  = sm;                    // [128][200]
    __nv_bfloat16* Ks  = Qs + 128 * 200;        // [64][200]
    __nv_bfloat16* Vh  = Ks + 64 * 200;         // [64][72]
    __nv_bfloat16* Vl  = Vh + 64 * 72;          // [64][72]
    float*         Msf = (float*)(Vl + 64 * 72);

    const int tid  = threadIdx.x;
    const int lane = tid & 31;
    const int warp = tid >> 5;
    const int g    = lane >> 2;
    const int tg   = lane & 3;
    const int bh   = blockIdx.y;
    const int b    = bh >> 4;
    const int hd   = bh & 15;
    const int q0   = blockIdx.x * 128;

    const __nv_bfloat16* qb  = q3  + ((size_t)bh * SEQ + q0) * 192;
    const __nv_bfloat16* kb  = k3  + (size_t)bh * SEQ * 192;
    const __nv_bfloat16* vhb = vhi + (size_t)bh * SEQ * HDIM;
    const __nv_bfloat16* vlb = vlo + (size_t)bh * SEQ * HDIM;
    const int* mk = mask + b * SEQ;

    // Q tile once: 128 rows x 192 bf16 = 3072 uint4
#pragma unroll 4
    for (int i = tid; i < 128 * 24; i += 128) {
        int r = i / 24, c = i % 24;
        *(uint4*)&Qs[r * 200 + c * 8] = *(const uint4*)&qb[r * 192 + c * 8];
    }

    float accO[2][8][4];
#pragma unroll
    for (int mi = 0; mi < 2; mi++)
#pragma unroll
        for (int ni = 0; ni < 8; ni++)
#pragma unroll
            for (int c = 0; c < 4; c++) accO[mi][ni][c] = 0.0f;
    float mrow[2][2] = {{-1e30f, -1e30f}, {-1e30f, -1e30f}};
    float lrow[2][2] = {{0.0f, 0.0f}, {0.0f, 0.0f}};

    for (int kt = 0; kt < SEQ; kt += 64) {
        // fill K/V/mask tiles
#pragma unroll 2
        for (int i = tid; i < 64 * 24; i += 128) {
            int r = i / 24, c = i % 24;
            *(uint4*)&Ks[r * 200 + c * 8] =
                *(const uint4*)&kb[(size_t)(kt + r) * 192 + c * 8];
        }
#pragma unroll 2
        for (int i = tid; i < 64 * 8; i += 128) {
            int r = i >> 3, c = i & 7;
            *(uint4*)&Vh[r * 72 + c * 8] =
                *(const uint4*)&vhb[(size_t)(kt + r) * HDIM + c * 8];
            *(uint4*)&Vl[r * 72 + c * 8] =
                *(const uint4*)&vlb[(size_t)(kt + r) * HDIM + c * 8];
        }
        if (tid < 64) Msf[tid] = mk[kt + tid] ? 0.0f : -1e30f;
        __syncthreads();

        // ---- S = Q3 @ K3^T  (k = 192, 12 steps)
        float S[2][8][4];
#pragma unroll
        for (int mi = 0; mi < 2; mi++)
#pragma unroll
            for (int ni = 0; ni < 8; ni++)
#pragma unroll
                for (int c = 0; c < 4; c++) S[mi][ni][c] = 0.0f;

#pragma unroll
        for (int ks = 0; ks < 12; ks++) {
            uint32_t a[2][4];
#pragma unroll
            for (int mi = 0; mi < 2; mi++) {
                uint32_t addr = smem_u32(
                    &Qs[(warp * 32 + mi * 16 + (lane & 15)) * 200
                        + ks * 16 + ((lane >> 4) << 3)]);
                asm volatile(
                    "ldmatrix.sync.aligned.m8n8.x4.shared.b16 {%0,%1,%2,%3}, [%4];"
                    : "=r"(a[mi][0]), "=r"(a[mi][1]), "=r"(a[mi][2]), "=r"(a[mi][3])
                    : "r"(addr));
            }
            uint32_t kf[8][2];
#pragma unroll
            for (int kq = 0; kq < 4; kq++) {
                uint32_t addr = smem_u32(
                    &Ks[(kq * 16 + (lane & 15)) * 200
                        + ks * 16 + ((lane >> 4) << 3)]);
                uint32_t t0, t1, t2, t3;
                asm volatile(
                    "ldmatrix.sync.aligned.m8n8.x4.shared.b16 {%0,%1,%2,%3}, [%4];"
                    : "=r"(t0), "=r"(t1), "=r"(t2), "=r"(t3)
                    : "r"(addr));
                // NON-trans B pairing: {t0,t2} -> ni, {t1,t3} -> ni+1
                kf[kq * 2][0]     = t0;  kf[kq * 2][1]     = t2;
                kf[kq * 2 + 1][0] = t1;  kf[kq * 2 + 1][1] = t3;
            }
#pragma unroll
            for (int mi = 0; mi < 2; mi++)
#pragma unroll
                for (int ni = 0; ni < 8; ni++)
                    asm volatile(
                        "mma.sync.aligned.m16n8k16.row.col.f32.bf16.bf16.f32 "
                        "{%0,%1,%2,%3}, {%4,%5,%6,%7}, {%8,%9}, {%0,%1,%2,%3};"
                        : "+f"(S[mi][ni][0]), "+f"(S[mi][ni][1]),
                          "+f"(S[mi][ni][2]), "+f"(S[mi][ni][3])
                        : "r"(a[mi][0]), "r"(a[mi][1]), "r"(a[mi][2]), "r"(a[mi][3]),
                          "r"(kf[ni][0]), "r"(kf[ni][1]));
        }

        // ---- mask add
        float msk[8][2];
#pragma unroll
        for (int ni = 0; ni < 8; ni++) {
            msk[ni][0] = Msf[ni * 8 + tg * 2];
            msk[ni][1] = Msf[ni * 8 + tg * 2 + 1];
        }
#pragma unroll
        for (int mi = 0; mi < 2; mi++)
#pragma unroll
            for (int ni = 0; ni < 8; ni++) {
                S[mi][ni][0] += msk[ni][0];
                S[mi][ni][1] += msk[ni][1];
                S[mi][ni][2] += msk[ni][0];
                S[mi][ni][3] += msk[ni][1];
            }

        // ---- row stats + O/l rescale (rows: (mi, g) and (mi, g+8))
#pragma unroll
        for (int mi = 0; mi < 2; mi++)
#pragma unroll
            for (int h = 0; h < 2; h++) {
                float rmax = -1e30f;
#pragma unroll
                for (int ni = 0; ni < 8; ni++)
                    rmax = fmaxf(rmax, fmaxf(S[mi][ni][h * 2], S[mi][ni][h * 2 + 1]));
                rmax = fmaxf(rmax, __shfl_xor_sync(0xffffffffu, rmax, 1));
                rmax = fmaxf(rmax, __shfl_xor_sync(0xffffffffu, rmax, 2));
                float mnew = fmaxf(mrow[mi][h], rmax);
                float corr = exp2f(mrow[mi][h] - mnew);
                mrow[mi][h] = mnew;
                lrow[mi][h] *= corr;
#pragma unroll
                for (int ni = 0; ni < 8; ni++) {
                    accO[mi][ni][h * 2]     *= corr;
                    accO[mi][ni][h * 2 + 1] *= corr;
                }
            }

        // ---- P = exp2(S - m); pack Phi/Plo as mma-A fragments
        uint32_t Ph[2][4][4], Pl[2][4][4];
#pragma unroll
        for (int mi = 0; mi < 2; mi++)
#pragma unroll
            for (int ks2 = 0; ks2 < 4; ks2++)
#pragma unroll
                for (int half = 0; half < 2; half++) {
                    const int ni = ks2 * 2 + half;
                    float p0 = exp2f(S[mi][ni][0] - mrow[mi][0]);
                    float p1 = exp2f(S[mi][ni][1] - mrow[mi][0]);
                    float p2 = exp2f(S[mi][ni][2] - mrow[mi][1]);
                    float p3 = exp2f(S[mi][ni][3] - mrow[mi][1]);
                    lrow[mi][0] += p0 + p1;
                    lrow[mi][1] += p2 + p3;
                    __nv_bfloat16 h0 = __float2bfloat16(p0);
                    __nv_bfloat16 h1 = __float2bfloat16(p1);
                    __nv_bfloat16 h2 = __float2bfloat16(p2);
                    __nv_bfloat16 h3 = __float2bfloat16(p3);
                    __nv_bfloat162 hi01 = __nv_bfloat162(h0, h1);
                    __nv_bfloat162 hi23 = __nv_bfloat162(h2, h3);
                    __nv_bfloat162 lo01 = __nv_bfloat162(
                        __float2bfloat16(p0 - __bfloat162float(h0)),
                        __float2bfloat16(p1 - __bfloat162float(h1)));
                    __nv_bfloat162 lo23 = __nv_bfloat162(
                        __float2bfloat16(p2 - __bfloat162float(h2)),
                        __float2bfloat16(p3 - __bfloat162float(h3)));
                    Ph[mi][ks2][half * 2]     = *(uint32_t*)&hi01;
                    Ph[mi][ks2][half * 2 + 1] = *(uint32_t*)&hi23;
                    Pl[mi][ks2][half * 2]     = *(uint32_t*)&lo01;
                    Pl[mi][ks2][half * 2 + 1] = *(uint32_t*)&lo23;
                }

        // ---- O += Phi@Vhi + Phi@Vlo + Plo@Vhi
#pragma unroll
        for (int pass = 0; pass < 3; pass++) {
            const __nv_bfloat16* Vt = (pass == 1) ? Vl : Vh;
#pragma unroll
            for (int ks2 = 0; ks2 < 4; ks2++) {
                uint32_t bo[8][2];
#pragma unroll
                for (int d16 = 0; d16 < 4; d16++) {
                    uint32_t addr = smem_u32(
                        &Vt[(ks2 * 16 + (lane & 15)) * 72
                            + d16 * 16 + ((lane >> 4) << 3)]);
                    uint32_t t0, t1, t2, t3;
                    asm volatile(
                        "ldmatrix.sync.aligned.m8n8.x4.trans.shared.b16 {%0,%1,%2,%3}, [%4];"
                        : "=r"(t0), "=r"(t1), "=r"(t2), "=r"(t3)
                        : "r"(addr));
                    bo[d16 * 2][0]     = t0;  bo[d16 * 2][1]     = t1;
                    bo[d16 * 2 + 1][0] = t2;  bo[d16 * 2 + 1][1] = t3;
                }
#pragma unroll
                for (int mi = 0; mi < 2; mi++) {
                    const uint32_t* af = (pass == 2) ? Pl[mi][ks2] : Ph[mi][ks2];
#pragma unroll
                    for (int ni = 0; ni < 8; ni++)
                        asm volatile(
                            "mma.sync.aligned.m16n8k16.row.col.f32.bf16.bf16.f32 "
                            "{%0,%1,%2,%3}, {%4,%5,%6,%7}, {%8,%9}, {%0,%1,%2,%3};"
                            : "+f"(accO[mi][ni][0]), "+f"(accO[mi][ni][1]),
                              "+f"(accO[mi][ni][2]), "+f"(accO[mi][ni][3])
                            : "r"(af[0]), "r"(af[1]), "r"(af[2]), "r"(af[3]),
                              "r"(bo[ni][0]), "r"(bo[ni][1]));
                }
            }
        }
        __syncthreads();
    }

    // ---- epilogue: reduce l over quad, normalize, store
    float inv[2][2];
#pragma unroll
    for (int mi = 0; mi < 2; mi++)
#pragma unroll
        for (int h = 0; h < 2; h++) {
            float ls = lrow[mi][h];
            ls += __shfl_xor_sync(0xffffffffu, ls, 1);
            ls += __shfl_xor_sync(0xffffffffu, ls, 2);
            inv[mi][h] = 1.0f / ls;
        }
#pragma unroll
    for (int mi = 0; mi < 2; mi++) {
        const int row0 = q0 + warp * 32 + mi * 16 + g;
#pragma unroll
        for (int ni = 0; ni < 8; ni++) {
            const int d = ni * 8 + tg * 2;
            float2 v0 = make_float2(accO[mi][ni][0] * inv[mi][0],
                                    accO[mi][ni][1] * inv[mi][0]);
            float2 v1 = make_float2(accO[mi][ni][2] * inv[mi][1],
                                    accO[mi][ni][3] * inv[mi][1]);
            *(float2*)&ctx[(size_t)(b * SEQ + row0) * EMBED + hd * HDIM + d]       = v0;
            *(float2*)&ctx[(size_t)(b * SEQ + row0 + 8) * EMBED + hd * HDIM + d]   = v1;
        }
    }
}

// ---------------------------------------------------------------------------
// Launch
// ---------------------------------------------------------------------------
extern "C" void kernel_launch(void* const* d_in, const int* in_sizes, int n_in,
                              void* d_out, int out_size)
{
    const float* x     = (const float*)d_in[0];
    const int*   mask  = (const int*)  d_in[1];
    const float* Wqkv  = (const float*)d_in[2];
    const float* bqkv  = (const float*)d_in[3];
    const float* Wout  = (const float*)d_in[4];
    const float* bout  = (const float*)d_in[5];
    float*       out   = (float*)d_out;

    float *qkv_ptr = nullptr, *ctx_ptr = nullptr;
    __nv_bfloat16 *a3 = nullptr, *w1 = nullptr, *w2 = nullptr;
    __nv_bfloat16 *q3 = nullptr, *k3 = nullptr, *vh = nullptr, *vl = nullptr;
    cudaGetSymbolAddress((void**)&qkv_ptr, g_qkv);
    cudaGetSymbolAddress((void**)&ctx_ptr, g_ctx);
    cudaGetSymbolAddress((void**)&a3, g_a3);
    cudaGetSymbolAddress((void**)&w1, g_w1);
    cudaGetSymbolAddress((void**)&w2, g_w2);
    cudaGetSymbolAddress((void**)&q3, g_q3);
    cudaGetSymbolAddress((void**)&k3, g_k3);
    cudaGetSymbolAddress((void**)&vh, g_vh);
    cudaGetSymbolAddress((void**)&vl, g_vl);

    static bool attr_set = false;
    if (!attr_set) {
        cudaFuncSetAttribute(attn_mma,
                             cudaFuncAttributeMaxDynamicSharedMemorySize, ATT_SMEM);
        attr_set = true;
    }

    // 1) split x and Wqkv into bf16x3 expanded operands
    split3_act<<<(MROWS * EMBED + 255) / 256, 256>>>(x, a3, MROWS, EMBED);
    split3_wt <<<(EMBED * 3 * EMBED + 255) / 256, 256>>>(Wqkv, w1, EMBED, 3 * EMBED);

    // 2) QKV projection on tensor cores: [8192,3072] @ [3072,3072] + b
    {
        dim3 grid((3 * EMBED) / GBN, MROWS / GBM);
        gemm_bf16_mma<<<grid, 256>>>(a3, w1, bqkv, qkv_ptr, MROWS, 3 * EMBED);
    }

    // 3) split qkv into per-head attention operands
    split_attn<<<(MROWS * EMBED + 255) / 256, 256>>>(qkv_ptr, q3, k3, vh, vl);

    // 4) Attention (FA2 mma, bf16x3)
    {
        dim3 grid(SEQ / 128, BATCH * NHEADS);
        attn_mma<<<grid, 128, ATT_SMEM>>>(q3, k3, vh, vl, mask, ctx_ptr);
    }

    // 5) split ctx and Wout
    split3_act<<<(MROWS * EMBED + 255) / 256, 256>>>(ctx_ptr, a3, MROWS, EMBED);
    split3_wt <<<(EMBED * EMBED + 255) / 256, 256>>>(Wout, w2, EMBED, EMBED);

    // 6) Output projection on tensor cores: [8192,3072] @ [3072,1024] + b
    {
        dim3 grid(EMBED / GBN, MROWS / GBM);
        gemm_bf16_mma<<<grid, 256>>>(a3, w2, bout, out, MROWS, EMBED);
    }
}

// round 8
// speedup vs baseline: 1.2180x; 1.2180x over previous
#include <cuda_runtime.h>
#include <cuda_bf16.h>
#include <cuda_pipeline.h>
#include <cstddef>
#include <cstdint>

// Problem constants
#define EMBED  1024
#define NHEADS 16
#define HDIM   64
#define BATCH  4
#define SEQ    2048
#define MROWS  (BATCH * SEQ)          // 8192
#define K3     (3 * EMBED)            // 3072 (bf16x3-split expanded K)

// ---------------------------------------------------------------------------
// Scratch (device globals: allocation-free per harness rules)
// ---------------------------------------------------------------------------
__device__ float          g_qkv[(size_t)MROWS * 3 * EMBED];     // GEMM1 out (f32)
__device__ __nv_bfloat16  g_a3[(size_t)MROWS * K3];             // split acts (x, then attn-out)
__device__ __nv_bfloat16  g_w1[(size_t)K3 * (3 * EMBED)];       // split Wqkv  [3072][3072]
__device__ __nv_bfloat16  g_w2[(size_t)K3 * EMBED];             // split Wout  [3072][1024]
// attention operands, head-contiguous [b*H+h][t][...]
__device__ __nv_bfloat16  g_q3[(size_t)BATCH * NHEADS * SEQ * 192];  // [Qhi|Qhi|Qlo] (pre-scaled)
__device__ __nv_bfloat16  g_k3[(size_t)BATCH * NHEADS * SEQ * 192];  // [Khi|Klo|Khi]
__device__ __nv_bfloat16  g_vh[(size_t)BATCH * NHEADS * SEQ * HDIM];
__device__ __nv_bfloat16  g_vl[(size_t)BATCH * NHEADS * SEQ * HDIM];

__device__ __forceinline__ uint32_t smem_u32(const void* p) {
    return (uint32_t)__cvta_generic_to_shared(p);
}

// ---------------------------------------------------------------------------
// bf16x3 split conversions (Markidis): v = hi + lo, error ~2^-18 rel
// ---------------------------------------------------------------------------
__global__ void split3_act(const float* __restrict__ src,
                           __nv_bfloat16* __restrict__ dst, int M, int K)
{
    int idx = blockIdx.x * blockDim.x + threadIdx.x;
    if (idx >= M * K) return;
    int m = idx / K, k = idx - m * K;
    float v = src[idx];
    __nv_bfloat16 hi = __float2bfloat16(v);
    __nv_bfloat16 lo = __float2bfloat16(v - __bfloat162float(hi));
    size_t base = (size_t)m * (3 * K);
    dst[base + k]         = hi;
    dst[base + K + k]     = hi;
    dst[base + 2 * K + k] = lo;
}

__global__ void split3_wt(const float* __restrict__ src,
                          __nv_bfloat16* __restrict__ dst, int K, int N)
{
    int idx = blockIdx.x * blockDim.x + threadIdx.x;
    if (idx >= K * N) return;
    int k = idx / N, n = idx - k * N;
    float v = src[idx];
    __nv_bfloat16 hi = __float2bfloat16(v);
    __nv_bfloat16 lo = __float2bfloat16(v - __bfloat162float(hi));
    dst[(size_t)k * N + n]           = hi;
    dst[(size_t)(K + k) * N + n]     = lo;
    dst[(size_t)(2 * K + k) * N + n] = hi;
}

// Split qkv (f32, [m][3072]) into per-head attention operands.
// Q is pre-scaled by (1/sqrt(d))*log2(e). One thread per (m, h, d).
__global__ void split_attn(const float* __restrict__ qkv,
                           __nv_bfloat16* __restrict__ q3,
                           __nv_bfloat16* __restrict__ k3,
                           __nv_bfloat16* __restrict__ vh,
                           __nv_bfloat16* __restrict__ vl)
{
    int idx = blockIdx.x * blockDim.x + threadIdx.x;
    if (idx >= MROWS * EMBED) return;
    int m = idx >> 10;                 // /1024
    int r = idx & 1023;
    int h = r >> 6;                    // /64
    int d = r & 63;
    int b = m / SEQ, t = m - b * SEQ;
    const float SC = 0.125f * 1.44269504088896340736f;

    float qv = qkv[(size_t)m * K3 + h * HDIM + d] * SC;
    float kv = qkv[(size_t)m * K3 + EMBED + h * HDIM + d];
    float vv = qkv[(size_t)m * K3 + 2 * EMBED + h * HDIM + d];

    size_t row = (size_t)(b * NHEADS + h) * SEQ + t;

    __nv_bfloat16 qh = __float2bfloat16(qv);
    __nv_bfloat16 ql = __float2bfloat16(qv - __bfloat162float(qh));
    q3[row * 192 + d]       = qh;
    q3[row * 192 + 64 + d]  = qh;
    q3[row * 192 + 128 + d] = ql;

    __nv_bfloat16 kh = __float2bfloat16(kv);
    __nv_bfloat16 kl = __float2bfloat16(kv - __bfloat162float(kh));
    k3[row * 192 + d]       = kh;
    k3[row * 192 + 64 + d]  = kl;
    k3[row * 192 + 128 + d] = kh;

    __nv_bfloat16 vhv = __float2bfloat16(vv);
    __nv_bfloat16 vlv = __float2bfloat16(vv - __bfloat162float(vhv));
    vh[row * HDIM + d] = vhv;
    vl[row * HDIM + d] = vlv;
}

// ---------------------------------------------------------------------------
// bf16 tensor-core GEMM + bias: now cp.async 3-stage pipelined.
// Tile/fragment/epilogue maps identical to benchmark-validated R5 kernel;
// only the GMEM->smem transport changed (LDGSTS, same smem image).
// ---------------------------------------------------------------------------
#define GBM 128
#define GBN 128
#define GBK 32
#define GSTG 3
#define AS_STRIDE (GBK + 8)            // 40 elems = 80B rows
#define BS_STRIDE (GBN + 8)            // 136 elems = 272B rows
#define AS_ELEMS  (GBM * AS_STRIDE)    // 5120
#define BS_ELEMS  (GBK * BS_STRIDE)    // 4352
#define GEMM_SMEM (GSTG * (AS_ELEMS + BS_ELEMS) * 2)   // 56832 B

__global__ __launch_bounds__(256, 2)
void gemm_bf16_mma(const __nv_bfloat16* __restrict__ A,   // [M][K3]
                   const __nv_bfloat16* __restrict__ B,   // [K3][N]
                   const float* __restrict__ bias,
                   float* __restrict__ C,
                   int M, int N)
{
    extern __shared__ __nv_bfloat16 gsm[];
    __nv_bfloat16* AsB = gsm;                       // [GSTG][128][40]
    __nv_bfloat16* BsB = gsm + GSTG * AS_ELEMS;     // [GSTG][32][136]

    const int tid  = threadIdx.x;
    const int lane = tid & 31;
    const int warp = tid >> 5;
    const int wm   = warp >> 2;
    const int wn   = warp & 3;
    const int bm   = blockIdx.y * GBM;
    const int bn   = blockIdx.x * GBN;

    const int ar0 = tid >> 2,          ac0 = (tid & 3) * 8;
    const int ar1 = 64 + (tid >> 2),   ac1 = (tid & 3) * 8;
    const int br0 = tid >> 4,          bc0 = (tid & 15) * 8;
    const int br1 = 16 + (tid >> 4),   bc1 = (tid & 15) * 8;

    const int ntiles = K3 / GBK;   // 96

    auto issue = [&](int t, int s) {
        __nv_bfloat16* Ad = AsB + s * AS_ELEMS;
        __nv_bfloat16* Bd = BsB + s * BS_ELEMS;
        const int k0 = t * GBK;
        __pipeline_memcpy_async(&Ad[ar0 * AS_STRIDE + ac0],
                                &A[(size_t)(bm + ar0) * K3 + k0 + ac0], 16);
        __pipeline_memcpy_async(&Ad[ar1 * AS_STRIDE + ac1],
                                &A[(size_t)(bm + ar1) * K3 + k0 + ac1], 16);
        __pipeline_memcpy_async(&Bd[br0 * BS_STRIDE + bc0],
                                &B[(size_t)(k0 + br0) * N + bn + bc0], 16);
        __pipeline_memcpy_async(&Bd[br1 * BS_STRIDE + bc1],
                                &B[(size_t)(k0 + br1) * N + bn + bc1], 16);
        __pipeline_commit();
    };

    float acc[4][4][4];
#pragma unroll
    for (int mi = 0; mi < 4; mi++)
#pragma unroll
        for (int ni = 0; ni < 4; ni++)
#pragma unroll
            for (int r = 0; r < 4; r++) acc[mi][ni][r] = 0.0f;

    issue(0, 0);
    issue(1, 1);

    for (int t = 0; t < ntiles; t++) {
        __pipeline_wait_prior(1);          // stage t resident (t+1 may be in flight)
        __syncthreads();                   // all readers of stage (t+2)%3 are done

        // prefetch t+2 into the freed stage, overlapping with compute below
        const int tn = t + 2;
        if (tn < ntiles) issue(tn, tn % GSTG);
        else             __pipeline_commit();   // keep commit count uniform

        const __nv_bfloat16* As = AsB + (t % GSTG) * AS_ELEMS;
        const __nv_bfloat16* Bs = BsB + (t % GSTG) * BS_ELEMS;

#pragma unroll
        for (int ks = 0; ks < 2; ks++) {
            const int k16 = ks * 16;
            uint32_t a[4][4];
#pragma unroll
            for (int mi = 0; mi < 4; mi++) {
                uint32_t addr = smem_u32(
                    &As[(wm * 64 + mi * 16 + (lane & 15)) * AS_STRIDE
                        + k16 + ((lane >> 4) << 3)]);
                asm volatile(
                    "ldmatrix.sync.aligned.m8n8.x4.shared.b16 {%0,%1,%2,%3}, [%4];"
                    : "=r"(a[mi][0]), "=r"(a[mi][1]), "=r"(a[mi][2]), "=r"(a[mi][3])
                    : "r"(addr));
            }
            uint32_t b[4][2];
#pragma unroll
            for (int n2 = 0; n2 < 2; n2++) {
                uint32_t addr = smem_u32(
                    &Bs[(k16 + (lane & 15)) * BS_STRIDE
                        + wn * 32 + n2 * 16 + ((lane >> 4) << 3)]);
                uint32_t t0, t1, t2, t3;
                asm volatile(
                    "ldmatrix.sync.aligned.m8n8.x4.trans.shared.b16 {%0,%1,%2,%3}, [%4];"
                    : "=r"(t0), "=r"(t1), "=r"(t2), "=r"(t3)
                    : "r"(addr));
                b[n2 * 2][0]     = t0;  b[n2 * 2][1]     = t1;
                b[n2 * 2 + 1][0] = t2;  b[n2 * 2 + 1][1] = t3;
            }
#pragma unroll
            for (int mi = 0; mi < 4; mi++)
#pragma unroll
                for (int ni = 0; ni < 4; ni++)
                    asm volatile(
                        "mma.sync.aligned.m16n8k16.row.col.f32.bf16.bf16.f32 "
                        "{%0,%1,%2,%3}, {%4,%5,%6,%7}, {%8,%9}, {%0,%1,%2,%3};"
                        : "+f"(acc[mi][ni][0]), "+f"(acc[mi][ni][1]),
                          "+f"(acc[mi][ni][2]), "+f"(acc[mi][ni][3])
                        : "r"(a[mi][0]), "r"(a[mi][1]), "r"(a[mi][2]), "r"(a[mi][3]),
                          "r"(b[ni][0]), "r"(b[ni][1]));
        }
    }

    const int g  = lane >> 2;
    const int tg = lane & 3;
#pragma unroll
    for (int mi = 0; mi < 4; mi++) {
        const int row0 = bm + wm * 64 + mi * 16 + g;
#pragma unroll
        for (int ni = 0; ni < 4; ni++) {
            const int col = bn + wn * 32 + ni * 8 + tg * 2;
            const float bx = bias[col], by = bias[col + 1];
            float2 v0 = make_float2(acc[mi][ni][0] + bx, acc[mi][ni][1] + by);
            float2 v1 = make_float2(acc[mi][ni][2] + bx, acc[mi][ni][3] + by);
            *(float2*)&C[(size_t)row0 * N + col]       = v0;
            *(float2*)&C[(size_t)(row0 + 8) * N + col] = v1;
        }
    }
}

// ---------------------------------------------------------------------------
// FA2-style attention, bf16x3, base-2 softmax (as R6: 256 threads, cp.async
// double-buffered K/V/mask, epilogue writes bf16x3 split directly into a3).
// smem: Qs[128][200] | Ks[2][64][200] | Vh[2][64][72] | Vl[2][64][72] | Msi[2][64]
// ---------------------------------------------------------------------------
#define ATT_SMEM (128*200*2 + 2*64*200*2 + 4*64*72*2 + 2*64*4)   // 139776 B

__global__ __launch_bounds__(256)
void attn_mma(const __nv_bfloat16* __restrict__ q3,
              const __nv_bfloat16* __restrict__ k3,
              const __nv_bfloat16* __restrict__ vhi,
              const __nv_bfloat16* __restrict__ vlo,
              const int* __restrict__ mask,
              __nv_bfloat16* __restrict__ a3)
{
    extern __shared__ char smraw[];
    __nv_bfloat16* Qs  = (__nv_bfloat16*)smraw;           // 128*200
    __nv_bfloat16* Ksb = Qs + 128 * 200;                  // 2 * 64*200
    __nv_bfloat16* Vhb = Ksb + 2 * 64 * 200;              // 2 * 64*72
    __nv_bfloat16* Vlb = Vhb + 2 * 64 * 72;               // 2 * 64*72
    int*           Msi = (int*)(Vlb + 2 * 64 * 72);       // 2 * 64

    const int tid  = threadIdx.x;
    const int lane = tid & 31;
    const int warp = tid >> 5;
    const int g    = lane >> 2;
    const int tg   = lane & 3;
    const int bh   = blockIdx.y;
    const int b    = bh >> 4;
    const int hd   = bh & 15;
    const int q0   = blockIdx.x * 128;

    const __nv_bfloat16* qb  = q3  + ((size_t)bh * SEQ + q0) * 192;
    const __nv_bfloat16* kb  = k3  + (size_t)bh * SEQ * 192;
    const __nv_bfloat16* vhb = vhi + (size_t)bh * SEQ * HDIM;
    const __nv_bfloat16* vlb = vlo + (size_t)bh * SEQ * HDIM;
    const int* mk = mask + b * SEQ;

    // Q tile once: 128 rows x 192 bf16 = 3072 uint4 (12 per thread)
#pragma unroll 4
    for (int i = tid; i < 128 * 24; i += 256) {
        int r = i / 24, c = i % 24;
        *(uint4*)&Qs[r * 200 + c * 8] = *(const uint4*)&qb[r * 192 + c * 8];
    }

    auto issue_tile = [&](int kt, int bufn) {
        __nv_bfloat16* Kd = Ksb + bufn * 64 * 200;
        __nv_bfloat16* Hd = Vhb + bufn * 64 * 72;
        __nv_bfloat16* Ld = Vlb + bufn * 64 * 72;
#pragma unroll 2
        for (int i = tid; i < 64 * 24; i += 256) {
            int r = i / 24, c = i % 24;
            __pipeline_memcpy_async(&Kd[r * 200 + c * 8],
                                    &kb[(size_t)(kt + r) * 192 + c * 8], 16);
        }
#pragma unroll 2
        for (int i = tid; i < 64 * 8; i += 256) {
            int r = i >> 3, c = i & 7;
            __pipeline_memcpy_async(&Hd[r * 72 + c * 8],
                                    &vhb[(size_t)(kt + r) * HDIM + c * 8], 16);
            __pipeline_memcpy_async(&Ld[r * 72 + c * 8],
                                    &vlb[(size_t)(kt + r) * HDIM + c * 8], 16);
        }
        if (tid < 16)
            __pipeline_memcpy_async(&Msi[bufn * 64 + tid * 4], &mk[kt + tid * 4], 16);
        __pipeline_commit();
    };

    float accO[8][4];
#pragma unroll
    for (int ni = 0; ni < 8; ni++)
#pragma unroll
        for (int c = 0; c < 4; c++) accO[ni][c] = 0.0f;
    float mrow[2] = {-1e30f, -1e30f};
    float lrow[2] = {0.0f, 0.0f};

    issue_tile(0, 0);

    int buf = 0;
    for (int kt = 0; kt < SEQ; kt += 64) {
        const bool has_next = (kt + 64) < SEQ;
        if (has_next) issue_tile(kt + 64, buf ^ 1);
        if (has_next) __pipeline_wait_prior(1);
        else          __pipeline_wait_prior(0);
        __syncthreads();

        const __nv_bfloat16* Ks = Ksb + buf * 64 * 200;
        const __nv_bfloat16* Vh = Vhb + buf * 64 * 72;
        const __nv_bfloat16* Vl = Vlb + buf * 64 * 72;
        const int*           Mi = Msi + buf * 64;

        // ---- S = Q3 @ K3^T  (k = 192, 12 steps), warp covers 16 q rows
        float S[8][4];
#pragma unroll
        for (int ni = 0; ni < 8; ni++)
#pragma unroll
            for (int c = 0; c < 4; c++) S[ni][c] = 0.0f;

#pragma unroll
        for (int ks = 0; ks < 12; ks++) {
            uint32_t a[4];
            {
                uint32_t addr = smem_u32(
                    &Qs[(warp * 16 + (lane & 15)) * 200
                        + ks * 16 + ((lane >> 4) << 3)]);
                asm volatile(
                    "ldmatrix.sync.aligned.m8n8.x4.shared.b16 {%0,%1,%2,%3}, [%4];"
                    : "=r"(a[0]), "=r"(a[1]), "=r"(a[2]), "=r"(a[3])
                    : "r"(addr));
            }
            uint32_t kf[8][2];
#pragma unroll
            for (int kq = 0; kq < 4; kq++) {
                uint32_t addr = smem_u32(
                    &Ks[(kq * 16 + (lane & 15)) * 200
                        + ks * 16 + ((lane >> 4) << 3)]);
                uint32_t t0, t1, t2, t3;
                asm volatile(
                    "ldmatrix.sync.aligned.m8n8.x4.shared.b16 {%0,%1,%2,%3}, [%4];"
                    : "=r"(t0), "=r"(t1), "=r"(t2), "=r"(t3)
                    : "r"(addr));
                // NON-trans B pairing: {t0,t2} -> ni, {t1,t3} -> ni+1
                kf[kq * 2][0]     = t0;  kf[kq * 2][1]     = t2;
                kf[kq * 2 + 1][0] = t1;  kf[kq * 2 + 1][1] = t3;
            }
#pragma unroll
            for (int ni = 0; ni < 8; ni++)
                asm volatile(
                    "mma.sync.aligned.m16n8k16.row.col.f32.bf16.bf16.f32 "
                    "{%0,%1,%2,%3}, {%4,%5,%6,%7}, {%8,%9}, {%0,%1,%2,%3};"
                    : "+f"(S[ni][0]), "+f"(S[ni][1]),
                      "+f"(S[ni][2]), "+f"(S[ni][3])
                    : "r"(a[0]), "r"(a[1]), "r"(a[2]), "r"(a[3]),
                      "r"(kf[ni][0]), "r"(kf[ni][1]));
        }

        // ---- mask add
#pragma unroll
        for (int ni = 0; ni < 8; ni++) {
            float m0 = Mi[ni * 8 + tg * 2]     ? 0.0f : -1e30f;
            float m1 = Mi[ni * 8 + tg * 2 + 1] ? 0.0f : -1e30f;
            S[ni][0] += m0;  S[ni][1] += m1;
            S[ni][2] += m0;  S[ni][3] += m1;
        }

        // ---- row stats + O/l rescale (rows g and g+8)
#pragma unroll
        for (int h = 0; h < 2; h++) {
            float rmax = -1e30f;
#pragma unroll
            for (int ni = 0; ni < 8; ni++)
                rmax = fmaxf(rmax, fmaxf(S[ni][h * 2], S[ni][h * 2 + 1]));
            rmax = fmaxf(rmax, __shfl_xor_sync(0xffffffffu, rmax, 1));
            rmax = fmaxf(rmax, __shfl_xor_sync(0xffffffffu, rmax, 2));
            float mnew = fmaxf(mrow[h], rmax);
            float corr = exp2f(mrow[h] - mnew);
            mrow[h] = mnew;
            lrow[h] *= corr;
#pragma unroll
            for (int ni = 0; ni < 8; ni++) {
                accO[ni][h * 2]     *= corr;
                accO[ni][h * 2 + 1] *= corr;
            }
        }

        // ---- P = exp2(S - m); pack Phi/Plo as mma-A fragments
        uint32_t Ph[4][4], Pl[4][4];
#pragma unroll
        for (int ks2 = 0; ks2 < 4; ks2++)
#pragma unroll
            for (int half = 0; half < 2; half++) {
                const int ni = ks2 * 2 + half;
                float p0 = exp2f(S[ni][0] - mrow[0]);
                float p1 = exp2f(S[ni][1] - mrow[0]);
                float p2 = exp2f(S[ni][2] - mrow[1]);
                float p3 = exp2f(S[ni][3] - mrow[1]);
                lrow[0] += p0 + p1;
                lrow[1] += p2 + p3;
                __nv_bfloat16 h0 = __float2bfloat16(p0);
                __nv_bfloat16 h1 = __float2bfloat16(p1);
                __nv_bfloat16 h2 = __float2bfloat16(p2);
                __nv_bfloat16 h3 = __float2bfloat16(p3);
                __nv_bfloat162 hi01 = __nv_bfloat162(h0, h1);
                __nv_bfloat162 hi23 = __nv_bfloat162(h2, h3);
                __nv_bfloat162 lo01 = __nv_bfloat162(
                    __float2bfloat16(p0 - __bfloat162float(h0)),
                    __float2bfloat16(p1 - __bfloat162float(h1)));
                __nv_bfloat162 lo23 = __nv_bfloat162(
                    __float2bfloat16(p2 - __bfloat162float(h2)),
                    __float2bfloat16(p3 - __bfloat162float(h3)));
                Ph[ks2][half * 2]     = *(uint32_t*)&hi01;
                Ph[ks2][half * 2 + 1] = *(uint32_t*)&hi23;
                Pl[ks2][half * 2]     = *(uint32_t*)&lo01;
                Pl[ks2][half * 2 + 1] = *(uint32_t*)&lo23;
            }

        // ---- O += Phi@Vhi + Phi@Vlo + Plo@Vhi
#pragma unroll
        for (int pass = 0; pass < 3; pass++) {
            const __nv_bfloat16* Vt = (pass == 1) ? Vl : Vh;
#pragma unroll
            for (int ks2 = 0; ks2 < 4; ks2++) {
                uint32_t bo[8][2];
#pragma unroll
                for (int d16 = 0; d16 < 4; d16++) {
                    uint32_t addr = smem_u32(
                        &Vt[(ks2 * 16 + (lane & 15)) * 72
                            + d16 * 16 + ((lane >> 4) << 3)]);
                    uint32_t t0, t1, t2, t3;
                    asm volatile(
                        "ldmatrix.sync.aligned.m8n8.x4.trans.shared.b16 {%0,%1,%2,%3}, [%4];"
                        : "=r"(t0), "=r"(t1), "=r"(t2), "=r"(t3)
                        : "r"(addr));
                    bo[d16 * 2][0]     = t0;  bo[d16 * 2][1]     = t1;
                    bo[d16 * 2 + 1][0] = t2;  bo[d16 * 2 + 1][1] = t3;
                }
                const uint32_t* af = (pass == 2) ? Pl[ks2] : Ph[ks2];
#pragma unroll
                for (int ni = 0; ni < 8; ni++)
                    asm volatile(
                        "mma.sync.aligned.m16n8k16.row.col.f32.bf16.bf16.f32 "
                        "{%0,%1,%2,%3}, {%4,%5,%6,%7}, {%8,%9}, {%0,%1,%2,%3};"
                        : "+f"(accO[ni][0]), "+f"(accO[ni][1]),
                          "+f"(accO[ni][2]), "+f"(accO[ni][3])
                        : "r"(af[0]), "r"(af[1]), "r"(af[2]), "r"(af[3]),
                          "r"(bo[ni][0]), "r"(bo[ni][1]));
            }
        }
        __syncthreads();
        buf ^= 1;
    }

    // ---- epilogue: reduce l over quad, normalize, bf16x3-split into a3
    float inv[2];
#pragma unroll
    for (int h = 0; h < 2; h++) {
        float ls = lrow[h];
        ls += __shfl_xor_sync(0xffffffffu, ls, 1);
        ls += __shfl_xor_sync(0xffffffffu, ls, 2);
        inv[h] = 1.0f / ls;
    }
    const int row0 = q0 + warp * 16 + g;
#pragma unroll
    for (int ni = 0; ni < 8; ni++) {
        const int d = ni * 8 + tg * 2;
#pragma unroll
        for (int h = 0; h < 2; h++) {
            float o0 = accO[ni][h * 2]     * inv[h];
            float o1 = accO[ni][h * 2 + 1] * inv[h];
            __nv_bfloat16 h0 = __float2bfloat16(o0);
            __nv_bfloat16 h1 = __float2bfloat16(o1);
            __nv_bfloat162 hi01 = __nv_bfloat162(h0, h1);
            __nv_bfloat162 lo01 = __nv_bfloat162(
                __float2bfloat16(o0 - __bfloat162float(h0)),
                __float2bfloat16(o1 - __bfloat162float(h1)));
            size_t base = ((size_t)(b * SEQ + row0 + h * 8)) * K3 + hd * HDIM + d;
            *(__nv_bfloat162*)&a3[base]        = hi01;
            *(__nv_bfloat162*)&a3[base + 1024] = hi01;
            *(__nv_bfloat162*)&a3[base + 2048] = lo01;
        }
    }
}

// ---------------------------------------------------------------------------
// Launch
// ---------------------------------------------------------------------------
extern "C" void kernel_launch(void* const* d_in, const int* in_sizes, int n_in,
                              void* d_out, int out_size)
{
    const float* x     = (const float*)d_in[0];
    const int*   mask  = (const int*)  d_in[1];
    const float* Wqkv  = (const float*)d_in[2];
    const float* bqkv  = (const float*)d_in[3];
    const float* Wout  = (const float*)d_in[4];
    const float* bout  = (const float*)d_in[5];
    float*       out   = (float*)d_out;

    float* qkv_ptr = nullptr;
    __nv_bfloat16 *a3 = nullptr, *w1 = nullptr, *w2 = nullptr;
    __nv_bfloat16 *q3 = nullptr, *k3 = nullptr, *vh = nullptr, *vl = nullptr;
    cudaGetSymbolAddress((void**)&qkv_ptr, g_qkv);
    cudaGetSymbolAddress((void**)&a3, g_a3);
    cudaGetSymbolAddress((void**)&w1, g_w1);
    cudaGetSymbolAddress((void**)&w2, g_w2);
    cudaGetSymbolAddress((void**)&q3, g_q3);
    cudaGetSymbolAddress((void**)&k3, g_k3);
    cudaGetSymbolAddress((void**)&vh, g_vh);
    cudaGetSymbolAddress((void**)&vl, g_vl);

    cudaFuncSetAttribute(attn_mma,
                         cudaFuncAttributeMaxDynamicSharedMemorySize, ATT_SMEM);
    cudaFuncSetAttribute(gemm_bf16_mma,
                         cudaFuncAttributeMaxDynamicSharedMemorySize, GEMM_SMEM);

    // 1) split x and Wqkv into bf16x3 expanded operands
    split3_act<<<(MROWS * EMBED + 255) / 256, 256>>>(x, a3, MROWS, EMBED);
    split3_wt <<<(EMBED * 3 * EMBED + 255) / 256, 256>>>(Wqkv, w1, EMBED, 3 * EMBED);

    // 2) QKV projection on tensor cores: [8192,3072] @ [3072,3072] + b
    {
        dim3 grid((3 * EMBED) / GBN, MROWS / GBM);
        gemm_bf16_mma<<<grid, 256, GEMM_SMEM>>>(a3, w1, bqkv, qkv_ptr, MROWS, 3 * EMBED);
    }

    // 3) split qkv into per-head attention operands
    split_attn<<<(MROWS * EMBED + 255) / 256, 256>>>(qkv_ptr, q3, k3, vh, vl);

    // 4) Attention (FA2 mma, bf16x3) — writes split a3 directly
    {
        dim3 grid(SEQ / 128, BATCH * NHEADS);
        attn_mma<<<grid, 256, ATT_SMEM>>>(q3, k3, vh, vl, mask, a3);
    }

    // 5) split Wout
    split3_wt <<<(EMBED * EMBED + 255) / 256, 256>>>(Wout, w2, EMBED, EMBED);

    // 6) Output projection on tensor cores: [8192,3072] @ [3072,1024] + b
    {
        dim3 grid(EMBED / GBN, MROWS / GBM);
        gemm_bf16_mma<<<grid, 256, GEMM_SMEM>>>(a3, w2, bout, out, MROWS, EMBED);
    }
}

// round 15
// speedup vs baseline: 1.3005x; 1.0677x over previous
#include <cuda_runtime.h>
#include <cuda_bf16.h>
#include <cuda_pipeline.h>
#include <cstddef>
#include <cstdint>

// Problem constants
#define EMBED  1024
#define NHEADS 16
#define HDIM   64
#define BATCH  4
#define SEQ    2048
#define MROWS  (BATCH * SEQ)          // 8192
#define K3     (3 * EMBED)            // 3072 (bf16x3-split expanded K)

// ---------------------------------------------------------------------------
// Scratch (device globals)
// ---------------------------------------------------------------------------
__device__ __nv_bfloat16  g_a3[(size_t)MROWS * K3];             // split acts (x, then attn-out)
__device__ __nv_bfloat16  g_w1[(size_t)K3 * (3 * EMBED)];       // split Wqkv
__device__ __nv_bfloat16  g_w2[(size_t)K3 * EMBED];             // split Wout
// attention operands, head-contiguous, deduplicated 128-col layout
__device__ __nv_bfloat16  g_q3[(size_t)BATCH * NHEADS * SEQ * 128];  // [Qhi|Qlo] (pre-scaled)
__device__ __nv_bfloat16  g_k3[(size_t)BATCH * NHEADS * SEQ * 128];  // [Khi|Klo]
__device__ __nv_bfloat16  g_vh[(size_t)BATCH * NHEADS * SEQ * HDIM];
__device__ __nv_bfloat16  g_vl[(size_t)BATCH * NHEADS * SEQ * HDIM];

__device__ __forceinline__ uint32_t smem_u32(const void* p) {
    return (uint32_t)__cvta_generic_to_shared(p);
}

// ---------------------------------------------------------------------------
// bf16x3 split conversions (Markidis): v = hi + lo, error ~2^-18 rel
// ---------------------------------------------------------------------------
__global__ void split3_act(const float* __restrict__ src,
                           __nv_bfloat16* __restrict__ dst, int M, int K)
{
    int idx = blockIdx.x * blockDim.x + threadIdx.x;
    if (idx >= M * K) return;
    int m = idx / K, k = idx - m * K;
    float v = src[idx];
    __nv_bfloat16 hi = __float2bfloat16(v);
    __nv_bfloat16 lo = __float2bfloat16(v - __bfloat162float(hi));
    size_t base = (size_t)m * (3 * K);
    dst[base + k]         = hi;
    dst[base + K + k]     = hi;
    dst[base + 2 * K + k] = lo;
}

__global__ void split3_wt(const float* __restrict__ src,
                          __nv_bfloat16* __restrict__ dst, int K, int N)
{
    int idx = blockIdx.x * blockDim.x + threadIdx.x;
    if (idx >= K * N) return;
    int k = idx / N, n = idx - k * N;
    float v = src[idx];
    __nv_bfloat16 hi = __float2bfloat16(v);
    __nv_bfloat16 lo = __float2bfloat16(v - __bfloat162float(hi));
    dst[(size_t)k * N + n]           = hi;
    dst[(size_t)(K + k) * N + n]     = lo;
    dst[(size_t)(2 * K + k) * N + n] = hi;
}

// ---------------------------------------------------------------------------
// bf16 tensor-core GEMM, cp.async 4-stage.  Epilogue templated:
//   SPLIT_QKV=false: C = A@B + bias (f32)
//   SPLIT_QKV=true : result split directly into q3/k3/vh/vl head-contiguous
//                    dedup bf16 hi/lo operands (Q pre-scaled).
// ---------------------------------------------------------------------------
#define GBM 128
#define GBN 128
#define GBK 32
#define GSTG 4
#define AS_STRIDE (GBK + 8)
#define BS_STRIDE (GBN + 8)
#define AS_ELEMS  (GBM * AS_STRIDE)
#define BS_ELEMS  (GBK * BS_STRIDE)
#define GEMM_SMEM (GSTG * (AS_ELEMS + BS_ELEMS) * 2)   // 75776 B

template<bool SPLIT_QKV>
__global__ __launch_bounds__(256, 2)
void gemm_bf16_mma(const __nv_bfloat16* __restrict__ A,   // [8192][K3]
                   const __nv_bfloat16* __restrict__ B,   // [K3][N]
                   const float* __restrict__ bias,
                   float* __restrict__ C,
                   __nv_bfloat16* __restrict__ q3,
                   __nv_bfloat16* __restrict__ k3,
                   __nv_bfloat16* __restrict__ vh,
                   __nv_bfloat16* __restrict__ vl,
                   int N)
{
    extern __shared__ __nv_bfloat16 gsm[];
    __nv_bfloat16* AsB = gsm;
    __nv_bfloat16* BsB = gsm + GSTG * AS_ELEMS;

    const int tid  = threadIdx.x;
    const int lane = tid & 31;
    const int warp = tid >> 5;
    const int wm   = warp >> 2;
    const int wn   = warp & 3;
    const int bm   = blockIdx.y * GBM;
    const int bn   = blockIdx.x * GBN;

    const int ar0 = tid >> 2,          ac0 = (tid & 3) * 8;
    const int ar1 = 64 + (tid >> 2),   ac1 = (tid & 3) * 8;
    const int br0 = tid >> 4,          bc0 = (tid & 15) * 8;
    const int br1 = 16 + (tid >> 4),   bc1 = (tid & 15) * 8;

    const int ntiles = K3 / GBK;   // 96

    auto issue = [&](int t, int s) {
        __nv_bfloat16* Ad = AsB + s * AS_ELEMS;
        __nv_bfloat16* Bd = BsB + s * BS_ELEMS;
        const int k0 = t * GBK;
        __pipeline_memcpy_async(&Ad[ar0 * AS_STRIDE + ac0],
                                &A[(size_t)(bm + ar0) * K3 + k0 + ac0], 16);
        __pipeline_memcpy_async(&Ad[ar1 * AS_STRIDE + ac1],
                                &A[(size_t)(bm + ar1) * K3 + k0 + ac1], 16);
        __pipeline_memcpy_async(&Bd[br0 * BS_STRIDE + bc0],
                                &B[(size_t)(k0 + br0) * N + bn + bc0], 16);
        __pipeline_memcpy_async(&Bd[br1 * BS_STRIDE + bc1],
                                &B[(size_t)(k0 + br1) * N + bn + bc1], 16);
        __pipeline_commit();
    };

    float acc[4][4][4];
#pragma unroll
    for (int mi = 0; mi < 4; mi++)
#pragma unroll
        for (int ni = 0; ni < 4; ni++)
#pragma unroll
            for (int r = 0; r < 4; r++) acc[mi][ni][r] = 0.0f;

    issue(0, 0);
    issue(1, 1);
    issue(2, 2);

    for (int t = 0; t < ntiles; t++) {
        __pipeline_wait_prior(2);
        __syncthreads();

        const int tn = t + 3;
        if (tn < ntiles) issue(tn, tn % GSTG);
        else             __pipeline_commit();

        const __nv_bfloat16* As = AsB + (t % GSTG) * AS_ELEMS;
        const __nv_bfloat16* Bs = BsB + (t % GSTG) * BS_ELEMS;

#pragma unroll
        for (int ks = 0; ks < 2; ks++) {
            const int k16 = ks * 16;
            uint32_t a[4][4];
#pragma unroll
            for (int mi = 0; mi < 4; mi++) {
                uint32_t addr = smem_u32(
                    &As[(wm * 64 + mi * 16 + (lane & 15)) * AS_STRIDE
                        + k16 + ((lane >> 4) << 3)]);
                asm volatile(
                    "ldmatrix.sync.aligned.m8n8.x4.shared.b16 {%0,%1,%2,%3}, [%4];"
                    : "=r"(a[mi][0]), "=r"(a[mi][1]), "=r"(a[mi][2]), "=r"(a[mi][3])
                    : "r"(addr));
            }
            uint32_t b[4][2];
#pragma unroll
            for (int n2 = 0; n2 < 2; n2++) {
                uint32_t addr = smem_u32(
                    &Bs[(k16 + (lane & 15)) * BS_STRIDE
                        + wn * 32 + n2 * 16 + ((lane >> 4) << 3)]);
                uint32_t t0, t1, t2, t3;
                asm volatile(
                    "ldmatrix.sync.aligned.m8n8.x4.trans.shared.b16 {%0,%1,%2,%3}, [%4];"
                    : "=r"(t0), "=r"(t1), "=r"(t2), "=r"(t3)
                    : "r"(addr));
                b[n2 * 2][0]     = t0;  b[n2 * 2][1]     = t1;
                b[n2 * 2 + 1][0] = t2;  b[n2 * 2 + 1][1] = t3;
            }
#pragma unroll
            for (int mi = 0; mi < 4; mi++)
#pragma unroll
                for (int ni = 0; ni < 4; ni++)
                    asm volatile(
                        "mma.sync.aligned.m16n8k16.row.col.f32.bf16.bf16.f32 "
                        "{%0,%1,%2,%3}, {%4,%5,%6,%7}, {%8,%9}, {%0,%1,%2,%3};"
                        : "+f"(acc[mi][ni][0]), "+f"(acc[mi][ni][1]),
                          "+f"(acc[mi][ni][2]), "+f"(acc[mi][ni][3])
                        : "r"(a[mi][0]), "r"(a[mi][1]), "r"(a[mi][2]), "r"(a[mi][3]),
                          "r"(b[ni][0]), "r"(b[ni][1]));
        }
    }

    const int g  = lane >> 2;
    const int tg = lane & 3;
#pragma unroll
    for (int mi = 0; mi < 4; mi++) {
        const int row0 = bm + wm * 64 + mi * 16 + g;
#pragma unroll
        for (int ni = 0; ni < 4; ni++) {
            const int col = bn + wn * 32 + ni * 8 + tg * 2;
            const float bx = bias[col], by = bias[col + 1];
            if constexpr (!SPLIT_QKV) {
                float2 v0 = make_float2(acc[mi][ni][0] + bx, acc[mi][ni][1] + by);
                float2 v1 = make_float2(acc[mi][ni][2] + bx, acc[mi][ni][3] + by);
                *(float2*)&C[(size_t)row0 * N + col]       = v0;
                *(float2*)&C[(size_t)(row0 + 8) * N + col] = v1;
            } else {
                const float SC = 0.125f * 1.44269504088896340736f;
                const int sec = col >> 10;          // 0=Q 1=K 2=V
                const int c   = col & 1023;
                const int h   = c >> 6;
                const int d   = c & 63;
#pragma unroll
                for (int rr = 0; rr < 2; rr++) {
                    const int row = row0 + rr * 8;
                    float v0 = acc[mi][ni][rr * 2]     + bx;
                    float v1 = acc[mi][ni][rr * 2 + 1] + by;
                    const int bb = row >> 11, tt = row & 2047;
                    const size_t arow = (size_t)(bb * NHEADS + h) * SEQ + tt;
                    if (sec == 0) { v0 *= SC; v1 *= SC; }
                    __nv_bfloat16 h0 = __float2bfloat16(v0);
                    __nv_bfloat16 h1 = __float2bfloat16(v1);
                    __nv_bfloat162 hi01 = __nv_bfloat162(h0, h1);
                    __nv_bfloat162 lo01 = __nv_bfloat162(
                        __float2bfloat16(v0 - __bfloat162float(h0)),
                        __float2bfloat16(v1 - __bfloat162float(h1)));
                    if (sec == 0) {
                        __nv_bfloat16* q = q3 + arow * 128 + d;
                        *(__nv_bfloat162*)(q)      = hi01;   // Qhi
                        *(__nv_bfloat162*)(q + 64) = lo01;   // Qlo
                    } else if (sec == 1) {
                        __nv_bfloat16* k = k3 + arow * 128 + d;
                        *(__nv_bfloat162*)(k)      = hi01;   // Khi
                        *(__nv_bfloat162*)(k + 64) = lo01;   // Klo
                    } else {
                        *(__nv_bfloat162*)&vh[arow * HDIM + d] = hi01;
                        *(__nv_bfloat162*)&vl[arow * HDIM + d] = lo01;
                    }
                }
            }
        }
    }
}

// ---------------------------------------------------------------------------
// FA2-style attention, bf16x3 via dedup [hi|lo] operands, base-2 softmax.
// 256 q-rows per CTA (8 warps x 32 rows); 12 k16-steps remapped onto 128-col
// storage: steps 0-3 Qhi*Khi, 4-7 Qhi*Klo, 8-11 Qlo*Khi — same pair sequence
// as the old 192-col layout, so S is bitwise identical.
// smem: Qs[256][136] | Ks[2][64][136] | Vh[2][64][72] | Vl[2][64][72] | Msi[2][64]
// ---------------------------------------------------------------------------
#define QK_STRIDE 136
#define ATT_SMEM (256*QK_STRIDE*2 + 2*64*QK_STRIDE*2 + 4*64*72*2 + 2*64*4)  // 141824 B

__global__ __launch_bounds__(256, 1)
void attn_mma(const __nv_bfloat16* __restrict__ q3,
              const __nv_bfloat16* __restrict__ k3,
              const __nv_bfloat16* __restrict__ vhi,
              const __nv_bfloat16* __restrict__ vlo,
              const int* __restrict__ mask,
              __nv_bfloat16* __restrict__ a3)
{
    extern __shared__ char smraw[];
    __nv_bfloat16* Qs  = (__nv_bfloat16*)smraw;              // 256*136
    __nv_bfloat16* Ksb = Qs + 256 * QK_STRIDE;               // 2 * 64*136
    __nv_bfloat16* Vhb = Ksb + 2 * 64 * QK_STRIDE;           // 2 * 64*72
    __nv_bfloat16* Vlb = Vhb + 2 * 64 * 72;                  // 2 * 64*72
    int*           Msi = (int*)(Vlb + 2 * 64 * 72);          // 2 * 64

    const int tid  = threadIdx.x;
    const int lane = tid & 31;
    const int warp = tid >> 5;
    const int g    = lane >> 2;
    const int tg   = lane & 3;
    const int bh   = blockIdx.y;
    const int b    = bh >> 4;
    const int hd   = bh & 15;
    const int q0   = blockIdx.x * 256;

    const __nv_bfloat16* qb  = q3  + ((size_t)bh * SEQ + q0) * 128;
    const __nv_bfloat16* kb  = k3  + (size_t)bh * SEQ * 128;
    const __nv_bfloat16* vhb = vhi + (size_t)bh * SEQ * HDIM;
    const __nv_bfloat16* vlb = vlo + (size_t)bh * SEQ * HDIM;
    const int* mk = mask + b * SEQ;

    // Q tile once: 256 rows x 128 bf16 = 4096 uint4 (16 per thread)
#pragma unroll 4
    for (int i = tid; i < 256 * 16; i += 256) {
        int r = i >> 4, c = i & 15;
        *(uint4*)&Qs[r * QK_STRIDE + c * 8] = *(const uint4*)&qb[r * 128 + c * 8];
    }

    auto issue_tile = [&](int kt, int bufn) {
        __nv_bfloat16* Kd = Ksb + bufn * 64 * QK_STRIDE;
        __nv_bfloat16* Hd = Vhb + bufn * 64 * 72;
        __nv_bfloat16* Ld = Vlb + bufn * 64 * 72;
#pragma unroll 2
        for (int i = tid; i < 64 * 16; i += 256) {
            int r = i >> 4, c = i & 15;
            __pipeline_memcpy_async(&Kd[r * QK_STRIDE + c * 8],
                                    &kb[(size_t)(kt + r) * 128 + c * 8], 16);
        }
#pragma unroll 2
        for (int i = tid; i < 64 * 8; i += 256) {
            int r = i >> 3, c = i & 7;
            __pipeline_memcpy_async(&Hd[r * 72 + c * 8],
                                    &vhb[(size_t)(kt + r) * HDIM + c * 8], 16);
            __pipeline_memcpy_async(&Ld[r * 72 + c * 8],
                                    &vlb[(size_t)(kt + r) * HDIM + c * 8], 16);
        }
        if (tid < 16)
            __pipeline_memcpy_async(&Msi[bufn * 64 + tid * 4], &mk[kt + tid * 4], 16);
        __pipeline_commit();
    };

    float accO[2][8][4];
#pragma unroll
    for (int mi = 0; mi < 2; mi++)
#pragma unroll
        for (int ni = 0; ni < 8; ni++)
#pragma unroll
            for (int c = 0; c < 4; c++) accO[mi][ni][c] = 0.0f;
    float mrow[2][2] = {{-1e30f, -1e30f}, {-1e30f, -1e30f}};
    float lrow[2][2] = {{0.0f, 0.0f}, {0.0f, 0.0f}};

    issue_tile(0, 0);

    int buf = 0;
    for (int kt = 0; kt < SEQ; kt += 64) {
        const bool has_next = (kt + 64) < SEQ;
        if (has_next) issue_tile(kt + 64, buf ^ 1);
        if (has_next) __pipeline_wait_prior(1);
        else          __pipeline_wait_prior(0);
        __syncthreads();

        const __nv_bfloat16* Ks = Ksb + buf * 64 * QK_STRIDE;
        const __nv_bfloat16* Vh = Vhb + buf * 64 * 72;
        const __nv_bfloat16* Vl = Vlb + buf * 64 * 72;
        const int*           Mi = Msi + buf * 64;

        // ---- S: 12 k16-steps over dedup [hi|lo] storage
        float S[2][8][4];
#pragma unroll
        for (int mi = 0; mi < 2; mi++)
#pragma unroll
            for (int ni = 0; ni < 8; ni++)
#pragma unroll
                for (int c = 0; c < 4; c++) S[mi][ni][c] = 0.0f;

#pragma unroll
        for (int ks = 0; ks < 12; ks++) {
            // column remap: steps 0-3 Qhi*Khi, 4-7 Qhi*Klo, 8-11 Qlo*Khi
            const int qc = (ks < 8) ? (ks & 3) * 16 : 64 + (ks & 3) * 16;
            const int kc = (ks < 4) ? ks * 16
                         : (ks < 8) ? 64 + (ks & 3) * 16
                                    : (ks & 3) * 16;
            uint32_t a[2][4];
#pragma unroll
            for (int mi = 0; mi < 2; mi++) {
                uint32_t addr = smem_u32(
                    &Qs[(warp * 32 + mi * 16 + (lane & 15)) * QK_STRIDE
                        + qc + ((lane >> 4) << 3)]);
                asm volatile(
                    "ldmatrix.sync.aligned.m8n8.x4.shared.b16 {%0,%1,%2,%3}, [%4];"
                    : "=r"(a[mi][0]), "=r"(a[mi][1]), "=r"(a[mi][2]), "=r"(a[mi][3])
                    : "r"(addr));
            }
            uint32_t kf[8][2];
#pragma unroll
            for (int kq = 0; kq < 4; kq++) {
                uint32_t addr = smem_u32(
                    &Ks[(kq * 16 + (lane & 15)) * QK_STRIDE
                        + kc + ((lane >> 4) << 3)]);
                uint32_t t0, t1, t2, t3;
                asm volatile(
                    "ldmatrix.sync.aligned.m8n8.x4.shared.b16 {%0,%1,%2,%3}, [%4];"
                    : "=r"(t0), "=r"(t1), "=r"(t2), "=r"(t3)
                    : "r"(addr));
                kf[kq * 2][0]     = t0;  kf[kq * 2][1]     = t2;
                kf[kq * 2 + 1][0] = t1;  kf[kq * 2 + 1][1] = t3;
            }
#pragma unroll
            for (int mi = 0; mi < 2; mi++)
#pragma unroll
                for (int ni = 0; ni < 8; ni++)
                    asm volatile(
                        "mma.sync.aligned.m16n8k16.row.col.f32.bf16.bf16.f32 "
                        "{%0,%1,%2,%3}, {%4,%5,%6,%7}, {%8,%9}, {%0,%1,%2,%3};"
                        : "+f"(S[mi][ni][0]), "+f"(S[mi][ni][1]),
                          "+f"(S[mi][ni][2]), "+f"(S[mi][ni][3])
                        : "r"(a[mi][0]), "r"(a[mi][1]), "r"(a[mi][2]), "r"(a[mi][3]),
                          "r"(kf[ni][0]), "r"(kf[ni][1]));
        }

        // ---- mask add + row stats + rescale
#pragma unroll
        for (int mi = 0; mi < 2; mi++)
#pragma unroll
            for (int ni = 0; ni < 8; ni++) {
                float m0 = Mi[ni * 8 + tg * 2]     ? 0.0f : -1e30f;
                float m1 = Mi[ni * 8 + tg * 2 + 1] ? 0.0f : -1e30f;
                S[mi][ni][0] += m0;  S[mi][ni][1] += m1;
                S[mi][ni][2] += m0;  S[mi][ni][3] += m1;
            }

#pragma unroll
        for (int mi = 0; mi < 2; mi++)
#pragma unroll
            for (int h = 0; h < 2; h++) {
                float rmax = -1e30f;
#pragma unroll
                for (int ni = 0; ni < 8; ni++)
                    rmax = fmaxf(rmax, fmaxf(S[mi][ni][h * 2], S[mi][ni][h * 2 + 1]));
                rmax = fmaxf(rmax, __shfl_xor_sync(0xffffffffu, rmax, 1));
                rmax = fmaxf(rmax, __shfl_xor_sync(0xffffffffu, rmax, 2));
                float mnew = fmaxf(mrow[mi][h], rmax);
                float corr = exp2f(mrow[mi][h] - mnew);
                mrow[mi][h] = mnew;
                lrow[mi][h] *= corr;
#pragma unroll
                for (int ni = 0; ni < 8; ni++) {
                    accO[mi][ni][h * 2]     *= corr;
                    accO[mi][ni][h * 2 + 1] *= corr;
                }
            }

        // ---- P = exp2(S - m); pack Phi/Plo as mma-A fragments
        uint32_t Ph[2][4][4], Pl[2][4][4];
#pragma unroll
        for (int mi = 0; mi < 2; mi++)
#pragma unroll
            for (int ks2 = 0; ks2 < 4; ks2++)
#pragma unroll
                for (int half = 0; half < 2; half++) {
                    const int ni = ks2 * 2 + half;
                    float p0 = exp2f(S[mi][ni][0] - mrow[mi][0]);
                    float p1 = exp2f(S[mi][ni][1] - mrow[mi][0]);
                    float p2 = exp2f(S[mi][ni][2] - mrow[mi][1]);
                    float p3 = exp2f(S[mi][ni][3] - mrow[mi][1]);
                    lrow[mi][0] += p0 + p1;
                    lrow[mi][1] += p2 + p3;
                    __nv_bfloat16 h0 = __float2bfloat16(p0);
                    __nv_bfloat16 h1 = __float2bfloat16(p1);
                    __nv_bfloat16 h2 = __float2bfloat16(p2);
                    __nv_bfloat16 h3 = __float2bfloat16(p3);
                    __nv_bfloat162 hi01 = __nv_bfloat162(h0, h1);
                    __nv_bfloat162 hi23 = __nv_bfloat162(h2, h3);
                    __nv_bfloat162 lo01 = __nv_bfloat162(
                        __float2bfloat16(p0 - __bfloat162float(h0)),
                        __float2bfloat16(p1 - __bfloat162float(h1)));
                    __nv_bfloat162 lo23 = __nv_bfloat162(
                        __float2bfloat16(p2 - __bfloat162float(h2)),
                        __float2bfloat16(p3 - __bfloat162float(h3)));
                    Ph[mi][ks2][half * 2]     = *(uint32_t*)&hi01;
                    Ph[mi][ks2][half * 2 + 1] = *(uint32_t*)&hi23;
                    Pl[mi][ks2][half * 2]     = *(uint32_t*)&lo01;
                    Pl[mi][ks2][half * 2 + 1] = *(uint32_t*)&lo23;
                }

        // ---- O += Phi@Vhi + Plo@Vhi (Vh frags reused) + Phi@Vlo
#pragma unroll
        for (int ks2 = 0; ks2 < 4; ks2++) {
            uint32_t bo[8][2];
#pragma unroll
            for (int d16 = 0; d16 < 4; d16++) {
                uint32_t addr = smem_u32(
                    &Vh[(ks2 * 16 + (lane & 15)) * 72
                        + d16 * 16 + ((lane >> 4) << 3)]);
                uint32_t t0, t1, t2, t3;
                asm volatile(
                    "ldmatrix.sync.aligned.m8n8.x4.trans.shared.b16 {%0,%1,%2,%3}, [%4];"
                    : "=r"(t0), "=r"(t1), "=r"(t2), "=r"(t3)
                    : "r"(addr));
                bo[d16 * 2][0]     = t0;  bo[d16 * 2][1]     = t1;
                bo[d16 * 2 + 1][0] = t2;  bo[d16 * 2 + 1][1] = t3;
            }
#pragma unroll
            for (int mi = 0; mi < 2; mi++)
#pragma unroll
                for (int ni = 0; ni < 8; ni++)
                    asm volatile(
                        "mma.sync.aligned.m16n8k16.row.col.f32.bf16.bf16.f32 "
                        "{%0,%1,%2,%3}, {%4,%5,%6,%7}, {%8,%9}, {%0,%1,%2,%3};"
                        : "+f"(accO[mi][ni][0]), "+f"(accO[mi][ni][1]),
                          "+f"(accO[mi][ni][2]), "+f"(accO[mi][ni][3])
                        : "r"(Ph[mi][ks2][0]), "r"(Ph[mi][ks2][1]),
                          "r"(Ph[mi][ks2][2]), "r"(Ph[mi][ks2][3]),
                          "r"(bo[ni][0]), "r"(bo[ni][1]));
#pragma unroll
            for (int mi = 0; mi < 2; mi++)
#pragma unroll
                for (int ni = 0; ni < 8; ni++)
                    asm volatile(
                        "mma.sync.aligned.m16n8k16.row.col.f32.bf16.bf16.f32 "
                        "{%0,%1,%2,%3}, {%4,%5,%6,%7}, {%8,%9}, {%0,%1,%2,%3};"
                        : "+f"(accO[mi][ni][0]), "+f"(accO[mi][ni][1]),
                          "+f"(accO[mi][ni][2]), "+f"(accO[mi][ni][3])
                        : "r"(Pl[mi][ks2][0]), "r"(Pl[mi][ks2][1]),
                          "r"(Pl[mi][ks2][2]), "r"(Pl[mi][ks2][3]),
                          "r"(bo[ni][0]), "r"(bo[ni][1]));
#pragma unroll
            for (int d16 = 0; d16 < 4; d16++) {
                uint32_t addr = smem_u32(
                    &Vl[(ks2 * 16 + (lane & 15)) * 72
                        + d16 * 16 + ((lane >> 4) << 3)]);
                uint32_t t0, t1, t2, t3;
                asm volatile(
                    "ldmatrix.sync.aligned.m8n8.x4.trans.shared.b16 {%0,%1,%2,%3}, [%4];"
                    : "=r"(t0), "=r"(t1), "=r"(t2), "=r"(t3)
                    : "r"(addr));
                bo[d16 * 2][0]     = t0;  bo[d16 * 2][1]     = t1;
                bo[d16 * 2 + 1][0] = t2;  bo[d16 * 2 + 1][1] = t3;
            }
#pragma unroll
            for (int mi = 0; mi < 2; mi++)
#pragma unroll
                for (int ni = 0; ni < 8; ni++)
                    asm volatile(
                        "mma.sync.aligned.m16n8k16.row.col.f32.bf16.bf16.f32 "
                        "{%0,%1,%2,%3}, {%4,%5,%6,%7}, {%8,%9}, {%0,%1,%2,%3};"
                        : "+f"(accO[mi][ni][0]), "+f"(accO[mi][ni][1]),
                          "+f"(accO[mi][ni][2]), "+f"(accO[mi][ni][3])
                        : "r"(Ph[mi][ks2][0]), "r"(Ph[mi][ks2][1]),
                          "r"(Ph[mi][ks2][2]), "r"(Ph[mi][ks2][3]),
                          "r"(bo[ni][0]), "r"(bo[ni][1]));
        }
        __syncthreads();
        buf ^= 1;
    }

    // ---- epilogue: reduce l over quad, normalize, bf16x3-split into a3
#pragma unroll
    for (int mi = 0; mi < 2; mi++) {
        float inv[2];
#pragma unroll
        for (int h = 0; h < 2; h++) {
            float ls = lrow[mi][h];
            ls += __shfl_xor_sync(0xffffffffu, ls, 1);
            ls += __shfl_xor_sync(0xffffffffu, ls, 2);
            inv[h] = 1.0f / ls;
        }
        const int row0 = q0 + warp * 32 + mi * 16 + g;
#pragma unroll
        for (int ni = 0; ni < 8; ni++) {
            const int d = ni * 8 + tg * 2;
#pragma unroll
            for (int h = 0; h < 2; h++) {
                float o0 = accO[mi][ni][h * 2]     * inv[h];
                float o1 = accO[mi][ni][h * 2 + 1] * inv[h];
                __nv_bfloat16 h0 = __float2bfloat16(o0);
                __nv_bfloat16 h1 = __float2bfloat16(o1);
                __nv_bfloat162 hi01 = __nv_bfloat162(h0, h1);
                __nv_bfloat162 lo01 = __nv_bfloat162(
                    __float2bfloat16(o0 - __bfloat162float(h0)),
                    __float2bfloat16(o1 - __bfloat162float(h1)));
                size_t base = ((size_t)(b * SEQ + row0 + h * 8)) * K3 + hd * HDIM + d;
                *(__nv_bfloat162*)&a3[base]        = hi01;
                *(__nv_bfloat162*)&a3[base + 1024] = hi01;
                *(__nv_bfloat162*)&a3[base + 2048] = lo01;
            }
        }
    }
}

// ---------------------------------------------------------------------------
// Launch
// ---------------------------------------------------------------------------
extern "C" void kernel_launch(void* const* d_in, const int* in_sizes, int n_in,
                              void* d_out, int out_size)
{
    const float* x     = (const float*)d_in[0];
    const int*   mask  = (const int*)  d_in[1];
    const float* Wqkv  = (const float*)d_in[2];
    const float* bqkv  = (const float*)d_in[3];
    const float* Wout  = (const float*)d_in[4];
    const float* bout  = (const float*)d_in[5];
    float*       out   = (float*)d_out;

    __nv_bfloat16 *a3 = nullptr, *w1 = nullptr, *w2 = nullptr;
    __nv_bfloat16 *q3 = nullptr, *k3 = nullptr, *vh = nullptr, *vl = nullptr;
    cudaGetSymbolAddress((void**)&a3, g_a3);
    cudaGetSymbolAddress((void**)&w1, g_w1);
    cudaGetSymbolAddress((void**)&w2, g_w2);
    cudaGetSymbolAddress((void**)&q3, g_q3);
    cudaGetSymbolAddress((void**)&k3, g_k3);
    cudaGetSymbolAddress((void**)&vh, g_vh);
    cudaGetSymbolAddress((void**)&vl, g_vl);

    cudaFuncSetAttribute(attn_mma,
                         cudaFuncAttributeMaxDynamicSharedMemorySize, ATT_SMEM);
    cudaFuncSetAttribute(gemm_bf16_mma<true>,
                         cudaFuncAttributeMaxDynamicSharedMemorySize, GEMM_SMEM);
    cudaFuncSetAttribute(gemm_bf16_mma<false>,
                         cudaFuncAttributeMaxDynamicSharedMemorySize, GEMM_SMEM);

    // 1) split x and Wqkv into bf16x3 expanded operands
    split3_act<<<(MROWS * EMBED + 255) / 256, 256>>>(x, a3, MROWS, EMBED);
    split3_wt <<<(EMBED * 3 * EMBED + 255) / 256, 256>>>(Wqkv, w1, EMBED, 3 * EMBED);

    // 2) QKV projection; epilogue splits directly into q3/k3/vh/vl
    {
        dim3 grid((3 * EMBED) / GBN, MROWS / GBM);
        gemm_bf16_mma<true><<<grid, 256, GEMM_SMEM>>>(
            a3, w1, bqkv, nullptr, q3, k3, vh, vl, 3 * EMBED);
    }

    // 3) Attention (FA2 mma, dedup bf16x3, 256-row q tiles) — writes split a3
    {
        dim3 grid(SEQ / 256, BATCH * NHEADS);
        attn_mma<<<grid, 256, ATT_SMEM>>>(q3, k3, vh, vl, mask, a3);
    }

    // 4) split Wout
    split3_wt <<<(EMBED * EMBED + 255) / 256, 256>>>(Wout, w2, EMBED, EMBED);

    // 5) Output projection: [8192,3072] @ [3072,1024] + b
    {
        dim3 grid(EMBED / GBN, MROWS / GBM);
        gemm_bf16_mma<false><<<grid, 256, GEMM_SMEM>>>(
            a3, w2, bout, out, nullptr, nullptr, nullptr, nullptr, EMBED);
    }
}